// round 8
// baseline (speedup 1.0000x reference)
#include <cuda_runtime.h>
#include <cstdint>

// SpikeFP32Tanh: [N,32] MSB-first 0/1 float bit-pulses -> tanh in FP64 ->
// [N,32] bit pulses.
//
// R8: exact R5 kernel (157.8us, DRAM 81%) with the 2^{j/64} table moved to
// COMPILE TIME: entries are constant-folded products of the same six hex
// constants C_b = 2^{2^b/64} (same multiply order as the runtime build that
// passed with rel_err 0.0 => bit-identical table). Kills the init kernel
// (~2.3us/replay) with zero runtime cost. Single launch.
//
// Math: E=exp(2v)=2^k*T[j]*expm1poly, m=E-1=fma(s,p,s-1), t=m/(m+2) via
// f32 rcp seed + 1 fp64 Newton. |v| clamped to 9.2 (exact for f32 tanh).

#define C1_  0x1.02c9a3e778061p+0   // 2^(1/64)
#define C2_  0x1.059b0d3158574p+0   // 2^(1/32)
#define C4_  0x1.0b5586cf9890fp+0   // 2^(1/16)
#define C8_  0x1.172b83c7d517bp+0   // 2^(1/8)
#define C16_ 0x1.306fe0a31b715p+0   // 2^(1/4)
#define C32_ 0x1.6a09e667f3bcdp+0   // 2^(1/2)

// Same left-to-right product order as the validated runtime build.
#define TV(j) ((((((((j)&1)?C1_:1.0) * (((j)&2)?C2_:1.0)) * (((j)&4)?C4_:1.0)) \
               * (((j)&8)?C8_:1.0)) * (((j)&16)?C16_:1.0)) * (((j)&32)?C32_:1.0))
#define TROW(b) TV(b),TV((b)+1),TV((b)+2),TV((b)+3),TV((b)+4),TV((b)+5),TV((b)+6),TV((b)+7)

__device__ const double g_T64[64] = {
    TROW(0),  TROW(8),  TROW(16), TROW(24),
    TROW(32), TROW(40), TROW(48), TROW(56)
};

__device__ __forceinline__ uint32_t spread4(uint32_t x) {
    // byte -> bit q goes to bit 4q
    x = (x | (x << 12)) & 0x000F000Fu;
    x = (x | (x << 6))  & 0x03030303u;
    x = (x | (x << 3))  & 0x11111111u;
    return x;
}

__global__ __launch_bounds__(256, 4)
void spike_tanh_kernel(const uint4* __restrict__ in4,
                       float4* __restrict__ out4,
                       int n)
{
    __shared__ double sT[64];
    if (threadIdx.x < 64) sT[threadIdx.x] = g_T64[threadIdx.x];
    __syncthreads();

    const unsigned FULL = 0xFFFFFFFFu;
    int warp_id = (blockIdx.x * blockDim.x + threadIdx.x) >> 5;
    int lane = threadIdx.x & 31;

    int elem_base = warp_id * 32;
    if (elem_base >= n) return;              // whole-warp uniform exit

    size_t base4 = (size_t)elem_base * 8;    // uint4 index of warp tile

    // ---- hoisted wide streaming loads: 8 outstanding LDG.128 per thread
    uint4 d[8];
#pragma unroll
    for (int t = 0; t < 8; ++t)
        d[t] = __ldcs(in4 + base4 + (size_t)t * 32 + lane);

    // ---- ballot-pack: 4 ballots per iteration, PRMT byte-gather by keeper
    const int jj = lane & 3;
    const int my_t = lane >> 2;
    const uint32_t s01 = (uint32_t)(jj | ((jj + 4) << 4));
    uint32_t bcs = 0u;
#pragma unroll
    for (int t = 0; t < 8; ++t) {
        uint32_t b0 = __ballot_sync(FULL, d[t].x != 0u);
        uint32_t b1 = __ballot_sync(FULL, d[t].y != 0u);
        uint32_t b2 = __ballot_sync(FULL, d[t].z != 0u);
        uint32_t b3 = __ballot_sync(FULL, d[t].w != 0u);
        if (my_t == t) {
            uint32_t p01 = __byte_perm(b0, b1, s01);
            uint32_t p23 = __byte_perm(b2, b3, s01);
            bcs = __byte_perm(p01, p23, 0x5410u);
        }
    }

    // ---- assemble MSB-first IEEE word
    uint32_t rev = spread4(bcs & 0xFFu)
                 | (spread4((bcs >> 8) & 0xFFu) << 1)
                 | (spread4((bcs >> 16) & 0xFFu) << 2)
                 | (spread4(bcs >> 24) << 3);
    uint32_t w = __brev(rev);

    // ---- custom FP64 tanh circuit (14 FP64-pipe ops)
    float vf = __uint_as_float(w);
    vf = fminf(fmaxf(vf, -9.2f), 9.2f);      // exact: |v|>9.015 -> tanh==+-1.0f
    double v = (double)vf;

    // n = round(2v / (ln2/64)) on the f32 pipe (|err| << 0.5)
    int ni = __float2int_rn(vf * 184.66497f);   // 128/ln2
    double nd = (double)ni;

    // Cody-Waite: h = v - n*(ln2/128)
    const double LH = 0x1.62e42feep-8;
    const double LL = 0x1.a39ef35793c76p-40;
    double h = fma(nd, -LH, v);
    h = fma(nd, -LL, h);

    // p = expm1(2h), |2h| <= ln2/128: Taylor through (2h)^6/720
    double q = fma(h, 4.0 / 45.0, 4.0 / 15.0);
    q = fma(h, q, 2.0 / 3.0);
    q = fma(h, q, 4.0 / 3.0);
    q = fma(h, q, 2.0);
    q = fma(h, q, 2.0);
    double p = q * h;

    // s = 2^(n>>6) * T[n&63] via exponent-field add (ALU, not FP64 pipe)
    long long tb = __double_as_longlong(sT[ni & 63]);
    tb += (long long)(ni >> 6) << 52;
    double s = __longlong_as_double(tb);

    double sm1 = s - 1.0;
    double m = fma(s, p, sm1);               // m = exp(2v) - 1, rel ~2^-46
    double den = m + 2.0;

    // t = m/den: f32 rcp seed + one fp64 Newton (rel ~2^-48)
    double r0 = (double)__frcp_rn((float)den);
    double e1 = fma(-den, r0, 1.0);
    double r1 = fma(r0, e1, r0);
    double t = m * r1;

    uint32_t o = __float_as_uint((float)t);

    // ---- scatter: 8 coalesced streaming STG.128, word routed by shuffle
    float4* row = out4 + base4;
#pragma unroll
    for (int k = 0; k < 8; ++k) {
        uint32_t ws = __shfl_sync(FULL, o, k * 4 + (lane >> 3));
        int b0 = (lane & 7) * 4;
        float4 f;
        f.x = ((ws >> (31 - b0)) & 1u) ? 1.0f : 0.0f;
        f.y = ((ws >> (30 - b0)) & 1u) ? 1.0f : 0.0f;
        f.z = ((ws >> (29 - b0)) & 1u) ? 1.0f : 0.0f;
        f.w = ((ws >> (28 - b0)) & 1u) ? 1.0f : 0.0f;
        __stcs(row + k * 32 + lane, f);
    }
}

extern "C" void kernel_launch(void* const* d_in, const int* in_sizes, int n_in,
                              void* d_out, int out_size)
{
    const uint4* in = (const uint4*)d_in[0];
    float4* out = (float4*)d_out;
    int n = in_sizes[0] / 32;                // number of scalar elements

    int block = 256;                         // 8 warps -> 256 elements/block
    int warps = n / 32;
    int grid = (warps + 7) / 8;
    spike_tanh_kernel<<<grid, block>>>(in, out, n);
}

// round 9
// speedup vs baseline: 1.8475x; 1.8475x over previous
#include <cuda_runtime.h>
#include <cstdint>

// SpikeFP32Tanh: [N,32] MSB-first 0/1 float bit-pulses -> tanh in FP64 ->
// [N,32] bit pulses.
//
// R9: single launch, R5's exact kernel body. Table 2^{j/64} is statically
// initialized at compile time (same constants/order as the validated runtime
// build) but declared NON-const __device__: a mutable .global symbol cannot
// be promoted to the constant bank, avoiding R8's catastrophic divergent-LDC
// serialization (32-way replay, +136us). Staging load stays LDG, table
// lookup stays LDS.
//
// Math: E=exp(2v)=2^k*T[j]*expm1poly, m=E-1=fma(s,p,s-1), t=m/(m+2) via
// f32 rcp seed + 1 fp64 Newton. |v| clamped to 9.2 (exact for f32 tanh).

#define C1_  0x1.02c9a3e778061p+0   // 2^(1/64)
#define C2_  0x1.059b0d3158574p+0   // 2^(1/32)
#define C4_  0x1.0b5586cf9890fp+0   // 2^(1/16)
#define C8_  0x1.172b83c7d517bp+0   // 2^(1/8)
#define C16_ 0x1.306fe0a31b715p+0   // 2^(1/4)
#define C32_ 0x1.6a09e667f3bcdp+0   // 2^(1/2)

// Same left-to-right product order as the validated runtime build.
#define TV(j) ((((((((j)&1)?C1_:1.0) * (((j)&2)?C2_:1.0)) * (((j)&4)?C4_:1.0)) \
               * (((j)&8)?C8_:1.0)) * (((j)&16)?C16_:1.0)) * (((j)&32)?C32_:1.0))
#define TROW(b) TV(b),TV((b)+1),TV((b)+2),TV((b)+3),TV((b)+4),TV((b)+5),TV((b)+6),TV((b)+7)

__device__ double g_T64[64] = {            // NON-const: must stay in .global
    TROW(0),  TROW(8),  TROW(16), TROW(24),
    TROW(32), TROW(40), TROW(48), TROW(56)
};

__device__ __forceinline__ uint32_t spread4(uint32_t x) {
    // byte -> bit q goes to bit 4q
    x = (x | (x << 12)) & 0x000F000Fu;
    x = (x | (x << 6))  & 0x03030303u;
    x = (x | (x << 3))  & 0x11111111u;
    return x;
}

__global__ __launch_bounds__(256, 4)
void spike_tanh_kernel(const uint4* __restrict__ in4,
                       float4* __restrict__ out4,
                       int n)
{
    __shared__ double sT[64];
    if (threadIdx.x < 64) sT[threadIdx.x] = g_T64[threadIdx.x];
    __syncthreads();

    const unsigned FULL = 0xFFFFFFFFu;
    int warp_id = (blockIdx.x * blockDim.x + threadIdx.x) >> 5;
    int lane = threadIdx.x & 31;

    int elem_base = warp_id * 32;
    if (elem_base >= n) return;              // whole-warp uniform exit

    size_t base4 = (size_t)elem_base * 8;    // uint4 index of warp tile

    // ---- hoisted wide streaming loads: 8 outstanding LDG.128 per thread
    uint4 d[8];
#pragma unroll
    for (int t = 0; t < 8; ++t)
        d[t] = __ldcs(in4 + base4 + (size_t)t * 32 + lane);

    // ---- ballot-pack: 4 ballots per iteration, PRMT byte-gather by keeper
    const int jj = lane & 3;
    const int my_t = lane >> 2;
    const uint32_t s01 = (uint32_t)(jj | ((jj + 4) << 4));
    uint32_t bcs = 0u;
#pragma unroll
    for (int t = 0; t < 8; ++t) {
        uint32_t b0 = __ballot_sync(FULL, d[t].x != 0u);
        uint32_t b1 = __ballot_sync(FULL, d[t].y != 0u);
        uint32_t b2 = __ballot_sync(FULL, d[t].z != 0u);
        uint32_t b3 = __ballot_sync(FULL, d[t].w != 0u);
        if (my_t == t) {
            uint32_t p01 = __byte_perm(b0, b1, s01);
            uint32_t p23 = __byte_perm(b2, b3, s01);
            bcs = __byte_perm(p01, p23, 0x5410u);
        }
    }

    // ---- assemble MSB-first IEEE word
    uint32_t rev = spread4(bcs & 0xFFu)
                 | (spread4((bcs >> 8) & 0xFFu) << 1)
                 | (spread4((bcs >> 16) & 0xFFu) << 2)
                 | (spread4(bcs >> 24) << 3);
    uint32_t w = __brev(rev);

    // ---- custom FP64 tanh circuit (14 FP64-pipe ops)
    float vf = __uint_as_float(w);
    vf = fminf(fmaxf(vf, -9.2f), 9.2f);      // exact: |v|>9.015 -> tanh==+-1.0f
    double v = (double)vf;

    // n = round(2v / (ln2/64)) on the f32 pipe (|err| << 0.5)
    int ni = __float2int_rn(vf * 184.66497f);   // 128/ln2
    double nd = (double)ni;

    // Cody-Waite: h = v - n*(ln2/128)
    const double LH = 0x1.62e42feep-8;
    const double LL = 0x1.a39ef35793c76p-40;
    double h = fma(nd, -LH, v);
    h = fma(nd, -LL, h);

    // p = expm1(2h), |2h| <= ln2/128: Taylor through (2h)^6/720
    double q = fma(h, 4.0 / 45.0, 4.0 / 15.0);
    q = fma(h, q, 2.0 / 3.0);
    q = fma(h, q, 4.0 / 3.0);
    q = fma(h, q, 2.0);
    q = fma(h, q, 2.0);
    double p = q * h;

    // s = 2^(n>>6) * T[n&63] via exponent-field add (ALU, not FP64 pipe)
    long long tb = __double_as_longlong(sT[ni & 63]);
    tb += (long long)(ni >> 6) << 52;
    double s = __longlong_as_double(tb);

    double sm1 = s - 1.0;
    double m = fma(s, p, sm1);               // m = exp(2v) - 1, rel ~2^-46
    double den = m + 2.0;

    // t = m/den: f32 rcp seed + one fp64 Newton (rel ~2^-48)
    double r0 = (double)__frcp_rn((float)den);
    double e1 = fma(-den, r0, 1.0);
    double r1 = fma(r0, e1, r0);
    double t = m * r1;

    uint32_t o = __float_as_uint((float)t);

    // ---- scatter: 8 coalesced streaming STG.128, word routed by shuffle
    float4* row = out4 + base4;
#pragma unroll
    for (int k = 0; k < 8; ++k) {
        uint32_t ws = __shfl_sync(FULL, o, k * 4 + (lane >> 3));
        int b0 = (lane & 7) * 4;
        float4 f;
        f.x = ((ws >> (31 - b0)) & 1u) ? 1.0f : 0.0f;
        f.y = ((ws >> (30 - b0)) & 1u) ? 1.0f : 0.0f;
        f.z = ((ws >> (29 - b0)) & 1u) ? 1.0f : 0.0f;
        f.w = ((ws >> (28 - b0)) & 1u) ? 1.0f : 0.0f;
        __stcs(row + k * 32 + lane, f);
    }
}

extern "C" void kernel_launch(void* const* d_in, const int* in_sizes, int n_in,
                              void* d_out, int out_size)
{
    const uint4* in = (const uint4*)d_in[0];
    float4* out = (float4*)d_out;
    int n = in_sizes[0] / 32;                // number of scalar elements

    int block = 256;                         // 8 warps -> 256 elements/block
    int warps = n / 32;
    int grid = (warps + 7) / 8;
    spike_tanh_kernel<<<grid, block>>>(in, out, n);
}

// round 10
// speedup vs baseline: 1.8700x; 1.0122x over previous
#include <cuda_runtime.h>
#include <cstdint>

// SpikeFP32Tanh: [N,32] MSB-first 0/1 float bit-pulses -> tanh in FP64 ->
// [N,32] bit pulses.
//
// R10: R9 (single launch, compile-time table in mutable .global, ballot
// transpose, 14-FP64-op tanh) with the residency cap raised from 4 to 6
// blocks/SM (regs=40 -> 1536 threads fit in the RF). More warps to cover
// HBM read/write turnaround + fewer waves (27.7 -> 18.5, smaller tail).
//
// Math: E=exp(2v)=2^k*T[j]*expm1poly, m=E-1=fma(s,p,s-1), t=m/(m+2) via
// f32 rcp seed + 1 fp64 Newton. |v| clamped to 9.2 (exact for f32 tanh).

#define C1_  0x1.02c9a3e778061p+0   // 2^(1/64)
#define C2_  0x1.059b0d3158574p+0   // 2^(1/32)
#define C4_  0x1.0b5586cf9890fp+0   // 2^(1/16)
#define C8_  0x1.172b83c7d517bp+0   // 2^(1/8)
#define C16_ 0x1.306fe0a31b715p+0   // 2^(1/4)
#define C32_ 0x1.6a09e667f3bcdp+0   // 2^(1/2)

// Same left-to-right product order as the validated runtime build.
#define TV(j) ((((((((j)&1)?C1_:1.0) * (((j)&2)?C2_:1.0)) * (((j)&4)?C4_:1.0)) \
               * (((j)&8)?C8_:1.0)) * (((j)&16)?C16_:1.0)) * (((j)&32)?C32_:1.0))
#define TROW(b) TV(b),TV((b)+1),TV((b)+2),TV((b)+3),TV((b)+4),TV((b)+5),TV((b)+6),TV((b)+7)

__device__ double g_T64[64] = {            // NON-const: must stay in .global
    TROW(0),  TROW(8),  TROW(16), TROW(24),
    TROW(32), TROW(40), TROW(48), TROW(56)
};

__device__ __forceinline__ uint32_t spread4(uint32_t x) {
    // byte -> bit q goes to bit 4q
    x = (x | (x << 12)) & 0x000F000Fu;
    x = (x | (x << 6))  & 0x03030303u;
    x = (x | (x << 3))  & 0x11111111u;
    return x;
}

__global__ __launch_bounds__(256, 6)
void spike_tanh_kernel(const uint4* __restrict__ in4,
                       float4* __restrict__ out4,
                       int n)
{
    __shared__ double sT[64];
    if (threadIdx.x < 64) sT[threadIdx.x] = g_T64[threadIdx.x];
    __syncthreads();

    const unsigned FULL = 0xFFFFFFFFu;
    int warp_id = (blockIdx.x * blockDim.x + threadIdx.x) >> 5;
    int lane = threadIdx.x & 31;

    int elem_base = warp_id * 32;
    if (elem_base >= n) return;              // whole-warp uniform exit

    size_t base4 = (size_t)elem_base * 8;    // uint4 index of warp tile

    // ---- hoisted wide streaming loads: 8 outstanding LDG.128 per thread
    uint4 d[8];
#pragma unroll
    for (int t = 0; t < 8; ++t)
        d[t] = __ldcs(in4 + base4 + (size_t)t * 32 + lane);

    // ---- ballot-pack: 4 ballots per iteration, PRMT byte-gather by keeper
    const int jj = lane & 3;
    const int my_t = lane >> 2;
    const uint32_t s01 = (uint32_t)(jj | ((jj + 4) << 4));
    uint32_t bcs = 0u;
#pragma unroll
    for (int t = 0; t < 8; ++t) {
        uint32_t b0 = __ballot_sync(FULL, d[t].x != 0u);
        uint32_t b1 = __ballot_sync(FULL, d[t].y != 0u);
        uint32_t b2 = __ballot_sync(FULL, d[t].z != 0u);
        uint32_t b3 = __ballot_sync(FULL, d[t].w != 0u);
        if (my_t == t) {
            uint32_t p01 = __byte_perm(b0, b1, s01);
            uint32_t p23 = __byte_perm(b2, b3, s01);
            bcs = __byte_perm(p01, p23, 0x5410u);
        }
    }

    // ---- assemble MSB-first IEEE word
    uint32_t rev = spread4(bcs & 0xFFu)
                 | (spread4((bcs >> 8) & 0xFFu) << 1)
                 | (spread4((bcs >> 16) & 0xFFu) << 2)
                 | (spread4(bcs >> 24) << 3);
    uint32_t w = __brev(rev);

    // ---- custom FP64 tanh circuit (14 FP64-pipe ops)
    float vf = __uint_as_float(w);
    vf = fminf(fmaxf(vf, -9.2f), 9.2f);      // exact: |v|>9.015 -> tanh==+-1.0f
    double v = (double)vf;

    // n = round(2v / (ln2/64)) on the f32 pipe (|err| << 0.5)
    int ni = __float2int_rn(vf * 184.66497f);   // 128/ln2
    double nd = (double)ni;

    // Cody-Waite: h = v - n*(ln2/128)
    const double LH = 0x1.62e42feep-8;
    const double LL = 0x1.a39ef35793c76p-40;
    double h = fma(nd, -LH, v);
    h = fma(nd, -LL, h);

    // p = expm1(2h), |2h| <= ln2/128: Taylor through (2h)^6/720
    double q = fma(h, 4.0 / 45.0, 4.0 / 15.0);
    q = fma(h, q, 2.0 / 3.0);
    q = fma(h, q, 4.0 / 3.0);
    q = fma(h, q, 2.0);
    q = fma(h, q, 2.0);
    double p = q * h;

    // s = 2^(n>>6) * T[n&63] via exponent-field add (ALU, not FP64 pipe)
    long long tb = __double_as_longlong(sT[ni & 63]);
    tb += (long long)(ni >> 6) << 52;
    double s = __longlong_as_double(tb);

    double sm1 = s - 1.0;
    double m = fma(s, p, sm1);               // m = exp(2v) - 1, rel ~2^-46
    double den = m + 2.0;

    // t = m/den: f32 rcp seed + one fp64 Newton (rel ~2^-48)
    double r0 = (double)__frcp_rn((float)den);
    double e1 = fma(-den, r0, 1.0);
    double r1 = fma(r0, e1, r0);
    double t = m * r1;

    uint32_t o = __float_as_uint((float)t);

    // ---- scatter: 8 coalesced streaming STG.128, word routed by shuffle
    float4* row = out4 + base4;
#pragma unroll
    for (int k = 0; k < 8; ++k) {
        uint32_t ws = __shfl_sync(FULL, o, k * 4 + (lane >> 3));
        int b0 = (lane & 7) * 4;
        float4 f;
        f.x = ((ws >> (31 - b0)) & 1u) ? 1.0f : 0.0f;
        f.y = ((ws >> (30 - b0)) & 1u) ? 1.0f : 0.0f;
        f.z = ((ws >> (29 - b0)) & 1u) ? 1.0f : 0.0f;
        f.w = ((ws >> (28 - b0)) & 1u) ? 1.0f : 0.0f;
        __stcs(row + k * 32 + lane, f);
    }
}

extern "C" void kernel_launch(void* const* d_in, const int* in_sizes, int n_in,
                              void* d_out, int out_size)
{
    const uint4* in = (const uint4*)d_in[0];
    float4* out = (float4*)d_out;
    int n = in_sizes[0] / 32;                // number of scalar elements

    int block = 256;                         // 8 warps -> 256 elements/block
    int warps = n / 32;
    int grid = (warps + 7) / 8;
    spike_tanh_kernel<<<grid, block>>>(in, out, n);
}